// round 10
// baseline (speedup 1.0000x reference)
#include <cuda_runtime.h>
#include <stdint.h>

#define NB   16384
#define FDIM 2048
#define HID  256
#define NODES 9
#define NSD  2304   // 9*256
#define NROW ((size_t)NB * NODES)   // 147456 total (b,node) rows

// ---------------- static scratch ----------------
__device__ float g_ns0[(size_t)NB * NSD];
__device__ float g_ns1[(size_t)NB * NSD];
__device__ float g_agg[(size_t)NB * NSD];
__device__ float g_ct [(size_t)NB * FDIM];   // tf32-rounded conc
__device__ float g_wt [(size_t)NSD * FDIM];  // tf32-rounded f2n_w
__device__ float g_wc [HID * 512];           // folded step weight (tf32-rounded)
__device__ float g_bc [HID];                 // folded step bias (fp32)

// ---------------- helpers ----------------
__device__ __forceinline__ float f2t(float x){
    uint32_t u; asm("cvt.rna.tf32.f32 %0, %1;" : "=r"(u) : "f"(x));
    return __uint_as_float(u);
}
__device__ __forceinline__ float4 f2t4(float4 v){
    v.x=f2t(v.x); v.y=f2t(v.y); v.z=f2t(v.z); v.w=f2t(v.w); return v;
}
__device__ __forceinline__ float4 f4add(float4 a, float4 b){
    a.x+=b.x; a.y+=b.y; a.z+=b.z; a.w+=b.w; return a;
}
__device__ __forceinline__ float4 f4sub(float4 a, float4 b){
    a.x-=b.x; a.y-=b.y; a.z-=b.z; a.w-=b.w; return a;
}
__device__ __forceinline__ float4 f4scale(float4 a, float s){
    a.x*=s; a.y*=s; a.z*=s; a.w*=s; return a;
}
__device__ __forceinline__ uint32_t smem_u32(const void* p){
    uint32_t a;
    asm("{ .reg .u64 t; cvta.to.shared.u64 t, %1; cvt.u32.u64 %0, t; }" : "=r"(a) : "l"(p));
    return a;
}
__device__ __forceinline__ void mma8(float c[4], const uint32_t a[4], uint32_t b0, uint32_t b1){
    asm volatile(
        "mma.sync.aligned.m16n8k8.row.col.f32.tf32.tf32.f32 "
        "{%0,%1,%2,%3},{%4,%5,%6,%7},{%8,%9},{%0,%1,%2,%3};\n"
        : "+f"(c[0]),"+f"(c[1]),"+f"(c[2]),"+f"(c[3])
        : "r"(a[0]),"r"(a[1]),"r"(a[2]),"r"(a[3]),"r"(b0),"r"(b1));
}
#define LDSM4(r0,r1,r2,r3,addr) \
    asm volatile("ldmatrix.sync.aligned.m8n8.x4.shared.b16 {%0,%1,%2,%3}, [%4];" \
        : "=r"(r0),"=r"(r1),"=r"(r2),"=r"(r3) : "r"(addr))

#define CP16(dst, src) asm volatile("cp.async.cg.shared.global [%0], [%1], 16;\n" :: "r"(dst), "l"(src))
#define CP_COMMIT()    asm volatile("cp.async.commit_group;\n" ::: "memory")
#define CP_WAIT2()     asm volatile("cp.async.wait_group 2;\n" ::: "memory")

// ---------------- weight folding ----------------
__global__ void prep_k(const float* __restrict__ msgw, const float* __restrict__ msgb,
                       const float* __restrict__ updw, const float* __restrict__ updb){
    int o = blockIdx.x, t = threadIdx.x;
    __shared__ float u2[HID];
    u2[t] = updw[o*512 + 256 + t];
    __syncthreads();
    g_wc[o*512 + t] = f2t(updw[o*512 + t]);
    float s = 0.f;
    #pragma unroll 8
    for (int j = 0; j < HID; j++) s += u2[j] * msgw[j*HID + t];
    g_wc[o*512 + 256 + t] = f2t(s);
    if (t == 0){
        float sb = 0.f;
        for (int j = 0; j < HID; j++) sb += u2[j] * msgb[j];
        g_bc[o] = updb[o] + sb;
    }
}

// ---------------- tf32 pre-rounding of GEMM inputs ----------------
__global__ void round_conc_k(const float* __restrict__ src){
    size_t i = (size_t)blockIdx.x*256 + threadIdx.x;
    ((float4*)g_ct)[i] = f2t4(((const float4*)src)[i]);
}
__global__ void round_w_k(const float* __restrict__ src){
    size_t i = (size_t)blockIdx.x*256 + threadIdx.x;
    ((float4*)g_wt)[i] = f2t4(((const float4*)src)[i]);
}

// ---------------- adjacency aggregation (only used ONCE, before step 0) ----------------
__global__ void __launch_bounds__(256) agg_k(int sel){
    const float* __restrict__ src = sel ? g_ns1 : g_ns0;
    int idx = blockIdx.x*256 + threadIdx.x;           // over NB*64
    int b = idx >> 6, h4 = (idx & 63) << 2;
    const float* base = src + (size_t)b*NSD + h4;
    float4 v[9];
    #pragma unroll
    for (int j = 0; j < 9; j++) v[j] = *(const float4*)(base + j*HID);
    float4 sall = v[0];
    #pragma unroll
    for (int j = 1; j < 9; j++) sall = f4add(sall, v[j]);
    float* ob = g_agg + (size_t)b*NSD + h4;
    *(float4*)(ob + 0*HID) = f2t4(f4scale(sall, 1.f/9.f));
    *(float4*)(ob + 1*HID) = f2t4(f4scale(f4add(v[0], v[1]), 0.5f));
    float4 b06 = f4add(v[0], f4add(v[7], v[8]));
    #pragma unroll
    for (int i = 2; i <= 6; i++)
        *(float4*)(ob + i*HID) = f2t4(f4scale(f4add(b06, v[i]), 0.25f));
    float4 r78 = f2t4(f4scale(f4sub(sall, v[1]), 0.125f));
    *(float4*)(ob + 7*HID) = r78;
    *(float4*)(ob + 8*HID) = r78;
}

// ---------------- tf32 mma.sync GEMM, L2-traffic-optimized ----------------
// 512 threads, 16 warps (2Mx8N), warp tile 64x32. 4-stage cp.async ring (221KB smem).
// MODE 0: CTA tile 128x256. g_ct[16384,2048] @ g_wt[2304,2048]^T + init epi -> g_ns0
// MODE 1: CTA tile 126(pad 128)x256, batch-aligned (14 batches/CTA).
//         [ns|agg][.,512] @ g_wc[256,512]^T, tanh; epilogue computes NEXT step's
//         adjacency aggregate on-chip and writes ns + agg together.
#define PADROW 144                 // bytes per 32-float k-row (LDSM conflict-free)
#define A_BYTES (128*PADROW)       // 18432
#define B_BYTES (256*PADROW)       // 36864
#define STAGE_BYTES (A_BYTES + B_BYTES)   // 55296
#define SMEM_TOTAL (4*STAGE_BYTES)        // 221184
#define SROW 260                   // smem Y-tile row stride in floats (65 float4)
template<int MODE>
__global__ void __launch_bounds__(512, 1) gemm_k(
    const float* __restrict__ f2nb, const float* __restrict__ logits,
    const float* __restrict__ encw, const float* __restrict__ encb,
    int sel, int write_agg)
{
    constexpr int KB = (MODE==0) ? FDIM : 512;
    constexpr int NC = KB / 32;

    extern __shared__ char smem_raw[];
    const uint32_t sbase = smem_u32(smem_raw);

    const int tid = threadIdx.x, wid = tid >> 5, lane = tid & 31;
    const int row0 = (MODE==0) ? blockIdx.y * 128 : blockIdx.y * 126;
    const int col0 = blockIdx.x * 256;   // MODE1: always 0

    // ---- global load mapping ----
    // threads 0..255: A (128 rows, 2 thr/row, 4x16B each)
    // threads 256..511: B (256 rows, 1 thr/row, 8x16B each)
    const bool isA = (tid < 256);
    const int arow = tid >> 1, aseg0 = (tid & 1) * 4;
    const int brow = tid - 256;
    const uint32_t adst0 = (uint32_t)arow*PADROW + (uint32_t)aseg0*16;
    const uint32_t bdst0 = A_BYTES + (uint32_t)(brow < 0 ? 0 : brow)*PADROW;

    const float* agp = nullptr; const float* agp2 = nullptr; const float* bgp = nullptr;
    if (isA){
        if constexpr (MODE == 0){
            agp = g_ct + (size_t)(row0 + arow)*FDIM + aseg0*4;
        } else {
            size_t gr = (size_t)row0 + arow;
            if (gr >= NROW) gr = NROW - 1;          // clamp tail/pad rows
            int b = (int)(gr / 9), n = (int)(gr - 9*(size_t)b);
            size_t base = (size_t)b*NSD + n*HID + aseg0*4;
            agp  = (sel ? g_ns1 : g_ns0) + base;
            agp2 = g_agg + base;
        }
    } else {
        if constexpr (MODE == 0) bgp = g_wt + (size_t)(col0 + brow)*FDIM;
        else                     bgp = g_wc + (size_t)brow*KB;
    }

    auto load_stage = [&](int s, int c){
        const uint32_t sb = sbase + (uint32_t)s*STAGE_BYTES;
        if (isA){
            const float* ap;
            if constexpr (MODE == 0) ap = agp + c*32;
            else                     ap = ((c < 8) ? agp : agp2) + (c & 7)*32;
            #pragma unroll
            for (int j = 0; j < 4; j++) CP16(sb + adst0 + j*16, ap + 4*j);
        } else {
            const float* bp = bgp + c*32;
            #pragma unroll
            for (int j = 0; j < 8; j++) CP16(sb + bdst0 + j*16, bp + 4*j);
        }
        CP_COMMIT();
    };

    // ---- fragment (ldmatrix) address setup: 16 warps = 2(M) x 8(N) ----
    const int mb = (wid & 1) * 64, nb = (wid >> 1) * 32;
    const int sub = lane >> 3;
    const int lrf = (sub & 1)*8 + (lane & 7);
    const int lca = (sub >> 1) * 16;
    uint32_t aoff[4];
    #pragma unroll
    for (int fm = 0; fm < 4; fm++)
        aoff[fm] = (uint32_t)(mb + fm*16 + lrf)*PADROW + lca;
    const int brf = (sub >> 1)*8 + (lane & 7);
    const int lcb = (sub & 1) * 16;
    uint32_t boff[2];
    #pragma unroll
    for (int p = 0; p < 2; p++)
        boff[p] = A_BYTES + (uint32_t)(nb + p*16 + brf)*PADROW + lcb;

    float acc[4][4][4];
    #pragma unroll
    for (int i=0;i<4;i++)
        #pragma unroll
        for (int j=0;j<4;j++)
            #pragma unroll
            for (int e=0;e<4;e++) acc[i][j][e] = 0.f;

    // ---- prologue: 3 of 4 stages in flight ----
    load_stage(0, 0); load_stage(1, 1); load_stage(2, 2);

    // ---- main loop ----
    for (int c = 0; c < NC; c++){
        CP_WAIT2();                 // all but 2 newest groups done -> chunk c landed
        __syncthreads();            // all warps past chunk c-1 -> stage (c+3)%4 free
        if (c + 3 < NC) load_stage((c + 3) % 4, c + 3);
        else            CP_COMMIT();   // keep group accounting uniform in tail

        const uint32_t stg = sbase + (uint32_t)(c & 3)*STAGE_BYTES;
        #pragma unroll
        for (int ks = 0; ks < 4; ks++){
            uint32_t a[4][4], b[4][2];
            #pragma unroll
            for (int fm = 0; fm < 4; fm++)
                LDSM4(a[fm][0], a[fm][1], a[fm][2], a[fm][3], stg + aoff[fm] + ks*32);
            #pragma unroll
            for (int p = 0; p < 2; p++)
                LDSM4(b[2*p][0], b[2*p][1], b[2*p+1][0], b[2*p+1][1], stg + boff[p] + ks*32);
            #pragma unroll
            for (int fm = 0; fm < 4; fm++)
                #pragma unroll
                for (int fn = 0; fn < 4; fn++)
                    mma8(acc[fm][fn], a[fm], b[fn][0], b[fn][1]);
        }
    }
    __syncthreads();   // everyone done with smem stages before epilogue reuse

    const int g = lane >> 2, tg = lane & 3;

    if constexpr (MODE == 0){
        // ---- init epilogue: + f2n_b + enc_b + logit*enc_w, straight to g_ns0 ----
        const int node = blockIdx.x;     // 256-col tile == one node
        #pragma unroll
        for (int fm = 0; fm < 4; fm++){
            const int gm = row0 + mb + fm*16 + g;
            const float lg0 = logits[gm*9 + node];
            const float lg1 = logits[(gm+8)*9 + node];
            float* dst0 = g_ns0 + (size_t)gm * NSD;
            float* dst1 = g_ns0 + (size_t)(gm + 8) * NSD;
            #pragma unroll
            for (int fn = 0; fn < 4; fn++){
                const int gn = col0 + nb + fn*8 + 2*tg;
                const int h = gn & 255;
                const float a0 = f2nb[gn]   + encb[h];
                const float a1 = f2nb[gn+1] + encb[h+1];
                const float e0 = encw[h], e1 = encw[h+1];
                float2 v0, v1;
                v0.x = f2t(acc[fm][fn][0] + a0 + lg0*e0);
                v0.y = f2t(acc[fm][fn][1] + a1 + lg0*e1);
                v1.x = f2t(acc[fm][fn][2] + a0 + lg1*e0);
                v1.y = f2t(acc[fm][fn][3] + a1 + lg1*e1);
                *(float2*)(dst0 + gn) = v0;
                *(float2*)(dst1 + gn) = v1;
            }
        }
    } else {
        // ---- step epilogue: tanh -> smem stage, then fused agg + stores ----
        float* sy = (float*)smem_raw;   // Y tile: 128 rows x SROW floats (133KB)
        #pragma unroll
        for (int fm = 0; fm < 4; fm++){
            const int r0l = mb + fm*16 + g;
            #pragma unroll
            for (int fn = 0; fn < 4; fn++){
                const int gn = nb + fn*8 + 2*tg;
                const float b0 = g_bc[gn], b1 = g_bc[gn+1];
                float2 v0, v1;
                v0.x = f2t(tanhf(acc[fm][fn][0] + b0));
                v0.y = f2t(tanhf(acc[fm][fn][1] + b1));
                v1.x = f2t(tanhf(acc[fm][fn][2] + b0));
                v1.y = f2t(tanhf(acc[fm][fn][3] + b1));
                *(float2*)(sy + (size_t)r0l*SROW + gn)     = v0;
                *(float2*)(sy + (size_t)(r0l+8)*SROW + gn) = v1;
            }
        }
        __syncthreads();

        float* dst = sel ? g_ns0 : g_ns1;
        const int nbat = (blockIdx.y*14 + 14 <= NB) ? 14 : (NB - blockIdx.y*14);
        // 14 batches x 64 col-quads = 896 items over 512 threads
        for (int idx = tid; idx < 14*64; idx += 512){
            const int lb = idx >> 6, c4 = (idx & 63) << 2;
            if (lb >= nbat) break;
            const size_t bglob = (size_t)(blockIdx.y*14 + lb);
            float4 v[9];
            #pragma unroll
            for (int j = 0; j < 9; j++)
                v[j] = *(float4*)(sy + (size_t)(lb*9 + j)*SROW + c4);
            float* nsb = dst + bglob*NSD + c4;
            #pragma unroll
            for (int j = 0; j < 9; j++)
                *(float4*)(nsb + j*HID) = v[j];
            if (write_agg){
                float4 sall = v[0];
                #pragma unroll
                for (int j = 1; j < 9; j++) sall = f4add(sall, v[j]);
                float* ab = g_agg + bglob*NSD + c4;
                *(float4*)(ab + 0*HID) = f2t4(f4scale(sall, 1.f/9.f));
                *(float4*)(ab + 1*HID) = f2t4(f4scale(f4add(v[0], v[1]), 0.5f));
                float4 b06 = f4add(v[0], f4add(v[7], v[8]));
                #pragma unroll
                for (int i = 2; i <= 6; i++)
                    *(float4*)(ab + i*HID) = f2t4(f4scale(f4add(b06, v[i]), 0.25f));
                float4 r78 = f2t4(f4scale(f4sub(sall, v[1]), 0.125f));
                *(float4*)(ab + 7*HID) = r78;
                *(float4*)(ab + 8*HID) = r78;
            }
        }
    }
}

// ---------------- output heads ----------------
__global__ void __launch_bounds__(256) out_k(const float* __restrict__ outw,
                                             const float* __restrict__ outb,
                                             float* __restrict__ out){
    int wid = threadIdx.x >> 5, lane = threadIdx.x & 31;
    int b = blockIdx.x * 8 + wid;
    const float* r7 = g_ns0 + (size_t)b*NSD + 7*HID;
    float s7 = 0.f, s8 = 0.f;
    #pragma unroll
    for (int i = lane; i < HID; i += 32){
        float w = outw[i];
        s7 += r7[i] * w;
        s8 += r7[i + HID] * w;
    }
    #pragma unroll
    for (int o = 16; o > 0; o >>= 1){
        s7 += __shfl_xor_sync(0xffffffffu, s7, o);
        s8 += __shfl_xor_sync(0xffffffffu, s8, o);
    }
    if (lane == 0){
        out[b]      = s7 + outb[0];
        out[NB + b] = s8 + outb[0];
    }
}

// ---------------- launch ----------------
extern "C" void kernel_launch(void* const* d_in, const int* in_sizes, int n_in,
                              void* d_out, int out_size){
    const float* conc   = (const float*)d_in[0];
    const float* logits = (const float*)d_in[1];
    const float* encw   = (const float*)d_in[2];
    const float* encb   = (const float*)d_in[3];
    const float* f2nw   = (const float*)d_in[4];
    const float* f2nb   = (const float*)d_in[5];
    const float* msgw   = (const float*)d_in[6];
    const float* msgb   = (const float*)d_in[7];
    const float* updw   = (const float*)d_in[8];
    const float* updb   = (const float*)d_in[9];
    const float* outw   = (const float*)d_in[10];
    const float* outb   = (const float*)d_in[11];
    float* out = (float*)d_out;

    cudaFuncSetAttribute(gemm_k<0>, cudaFuncAttributeMaxDynamicSharedMemorySize, SMEM_TOTAL);
    cudaFuncSetAttribute(gemm_k<1>, cudaFuncAttributeMaxDynamicSharedMemorySize, SMEM_TOTAL);

    prep_k<<<256, 256>>>(msgw, msgb, updw, updb);
    round_conc_k<<<(NB*(FDIM/4))/256, 256>>>(conc);
    round_w_k<<<(NSD*(FDIM/4))/256, 256>>>(f2nw);

    // init: node_states -> g_ns0  (grid: 9 N-blocks x 128 M-blocks)
    gemm_k<0><<<dim3(NSD/256, NB/128), 512, SMEM_TOTAL>>>(f2nb, logits, encw, encb, 0, 0);

    // first aggregate (from initial states)
    agg_k<<<(NB*64)/256, 256>>>(0);

    // 4 steps; ping-pong ns0/ns1; steps 0..2 also emit next step's agg in-epilogue
    const int MB1 = (NB + 13) / 14;   // 1171 batch-aligned M-blocks
    for (int s = 0; s < 4; s++){
        gemm_k<1><<<dim3(1, MB1), 512, SMEM_TOTAL>>>(nullptr, nullptr, nullptr, nullptr,
                                                     s & 1, (s < 3) ? 1 : 0);
    }

    out_k<<<NB/8, 256>>>(outw, outb, out);
}

// round 11
// speedup vs baseline: 1.0001x; 1.0001x over previous
#include <cuda_runtime.h>
#include <stdint.h>

#define NB   16384
#define FDIM 2048
#define HID  256
#define NODES 9
#define NSD  2304   // 9*256
#define NROW ((size_t)NB * NODES)   // 147456 total (b,node) rows

// ---------------- static scratch ----------------
__device__ float g_ns0[(size_t)NB * NSD];
__device__ float g_ns1[(size_t)NB * NSD];
__device__ float g_agg[(size_t)NB * NSD];
__device__ float g_ct [(size_t)NB * FDIM];   // tf32-rounded conc
__device__ float g_wt [(size_t)NSD * FDIM];  // tf32-rounded f2n_w
__device__ float g_wc [HID * 512];           // folded step weight (tf32-rounded)
__device__ float g_bc [HID];                 // folded step bias (fp32)

// ---------------- helpers ----------------
__device__ __forceinline__ float f2t(float x){
    uint32_t u; asm("cvt.rna.tf32.f32 %0, %1;" : "=r"(u) : "f"(x));
    return __uint_as_float(u);
}
__device__ __forceinline__ float4 f2t4(float4 v){
    v.x=f2t(v.x); v.y=f2t(v.y); v.z=f2t(v.z); v.w=f2t(v.w); return v;
}
__device__ __forceinline__ float4 f4add(float4 a, float4 b){
    a.x+=b.x; a.y+=b.y; a.z+=b.z; a.w+=b.w; return a;
}
__device__ __forceinline__ float4 f4sub(float4 a, float4 b){
    a.x-=b.x; a.y-=b.y; a.z-=b.z; a.w-=b.w; return a;
}
__device__ __forceinline__ float4 f4scale(float4 a, float s){
    a.x*=s; a.y*=s; a.z*=s; a.w*=s; return a;
}
__device__ __forceinline__ uint32_t smem_u32(const void* p){
    uint32_t a;
    asm("{ .reg .u64 t; cvta.to.shared.u64 t, %1; cvt.u32.u64 %0, t; }" : "=r"(a) : "l"(p));
    return a;
}
__device__ __forceinline__ void mma8(float c[4], const uint32_t a[4], uint32_t b0, uint32_t b1){
    asm volatile(
        "mma.sync.aligned.m16n8k8.row.col.f32.tf32.tf32.f32 "
        "{%0,%1,%2,%3},{%4,%5,%6,%7},{%8,%9},{%0,%1,%2,%3};\n"
        : "+f"(c[0]),"+f"(c[1]),"+f"(c[2]),"+f"(c[3])
        : "r"(a[0]),"r"(a[1]),"r"(a[2]),"r"(a[3]),"r"(b0),"r"(b1));
}
#define LDSM4(r0,r1,r2,r3,addr) \
    asm volatile("ldmatrix.sync.aligned.m8n8.x4.shared.b16 {%0,%1,%2,%3}, [%4];" \
        : "=r"(r0),"=r"(r1),"=r"(r2),"=r"(r3) : "r"(addr))

#define CP16(dst, src) asm volatile("cp.async.cg.shared.global [%0], [%1], 16;\n" :: "r"(dst), "l"(src))
#define CP_COMMIT()    asm volatile("cp.async.commit_group;\n" ::: "memory")
#define CP_WAIT2()     asm volatile("cp.async.wait_group 2;\n" ::: "memory")

// ---------------- weight folding ----------------
__global__ void prep_k(const float* __restrict__ msgw, const float* __restrict__ msgb,
                       const float* __restrict__ updw, const float* __restrict__ updb){
    int o = blockIdx.x, t = threadIdx.x;
    __shared__ float u2[HID];
    u2[t] = updw[o*512 + 256 + t];
    __syncthreads();
    g_wc[o*512 + t] = f2t(updw[o*512 + t]);
    float s = 0.f;
    #pragma unroll 8
    for (int j = 0; j < HID; j++) s += u2[j] * msgw[j*HID + t];
    g_wc[o*512 + 256 + t] = f2t(s);
    if (t == 0){
        float sb = 0.f;
        for (int j = 0; j < HID; j++) sb += u2[j] * msgb[j];
        g_bc[o] = updb[o] + sb;
    }
}

// ---------------- tf32 pre-rounding of GEMM inputs ----------------
__global__ void round_conc_k(const float* __restrict__ src){
    size_t i = (size_t)blockIdx.x*256 + threadIdx.x;
    ((float4*)g_ct)[i] = f2t4(((const float4*)src)[i]);
}
__global__ void round_w_k(const float* __restrict__ src){
    size_t i = (size_t)blockIdx.x*256 + threadIdx.x;
    ((float4*)g_wt)[i] = f2t4(((const float4*)src)[i]);
}

// ---------------- adjacency aggregation (only used ONCE, before step 0) ----------------
__global__ void __launch_bounds__(256) agg_k(int sel){
    const float* __restrict__ src = sel ? g_ns1 : g_ns0;
    int idx = blockIdx.x*256 + threadIdx.x;           // over NB*64
    int b = idx >> 6, h4 = (idx & 63) << 2;
    const float* base = src + (size_t)b*NSD + h4;
    float4 v[9];
    #pragma unroll
    for (int j = 0; j < 9; j++) v[j] = *(const float4*)(base + j*HID);
    float4 sall = v[0];
    #pragma unroll
    for (int j = 1; j < 9; j++) sall = f4add(sall, v[j]);
    float* ob = g_agg + (size_t)b*NSD + h4;
    *(float4*)(ob + 0*HID) = f2t4(f4scale(sall, 1.f/9.f));
    *(float4*)(ob + 1*HID) = f2t4(f4scale(f4add(v[0], v[1]), 0.5f));
    float4 b06 = f4add(v[0], f4add(v[7], v[8]));
    #pragma unroll
    for (int i = 2; i <= 6; i++)
        *(float4*)(ob + i*HID) = f2t4(f4scale(f4add(b06, v[i]), 0.25f));
    float4 r78 = f2t4(f4scale(f4sub(sall, v[1]), 0.125f));
    *(float4*)(ob + 7*HID) = r78;
    *(float4*)(ob + 8*HID) = r78;
}

// ---------------- tf32 mma.sync GEMM, L2-traffic-optimized ----------------
// 512 threads, 16 warps (2Mx8N), warp tile 64x32. 4-stage cp.async ring (221KB smem).
// MODE 0: CTA tile 128x256. g_ct[16384,2048] @ g_wt[2304,2048]^T + init epi -> g_ns0
// MODE 1: CTA tile 126(pad 128)x256, batch-aligned (14 batches/CTA).
//         [ns|agg][.,512] @ g_wc[256,512]^T, tanh; epilogue computes NEXT step's
//         adjacency aggregate on-chip and writes ns + agg together.
#define PADROW 144                 // bytes per 32-float k-row (LDSM conflict-free)
#define A_BYTES (128*PADROW)       // 18432
#define B_BYTES (256*PADROW)       // 36864
#define STAGE_BYTES (A_BYTES + B_BYTES)   // 55296
#define SMEM_TOTAL (4*STAGE_BYTES)        // 221184
#define SROW 260                   // smem Y-tile row stride in floats (65 float4)
template<int MODE>
__global__ void __launch_bounds__(512, 1) gemm_k(
    const float* __restrict__ f2nb, const float* __restrict__ logits,
    const float* __restrict__ encw, const float* __restrict__ encb,
    int sel, int write_agg)
{
    constexpr int KB = (MODE==0) ? FDIM : 512;
    constexpr int NC = KB / 32;

    extern __shared__ char smem_raw[];
    const uint32_t sbase = smem_u32(smem_raw);

    const int tid = threadIdx.x, wid = tid >> 5, lane = tid & 31;
    const int row0 = (MODE==0) ? blockIdx.y * 128 : blockIdx.y * 126;
    const int col0 = blockIdx.x * 256;   // MODE1: always 0

    // ---- global load mapping ----
    // threads 0..255: A (128 rows, 2 thr/row, 4x16B each)
    // threads 256..511: B (256 rows, 1 thr/row, 8x16B each)
    const bool isA = (tid < 256);
    const int arow = tid >> 1, aseg0 = (tid & 1) * 4;
    const int brow = tid - 256;
    const uint32_t adst0 = (uint32_t)arow*PADROW + (uint32_t)aseg0*16;
    const uint32_t bdst0 = A_BYTES + (uint32_t)(brow < 0 ? 0 : brow)*PADROW;

    const float* agp = nullptr; const float* agp2 = nullptr; const float* bgp = nullptr;
    if (isA){
        if constexpr (MODE == 0){
            agp = g_ct + (size_t)(row0 + arow)*FDIM + aseg0*4;
        } else {
            size_t gr = (size_t)row0 + arow;
            if (gr >= NROW) gr = NROW - 1;          // clamp tail/pad rows
            int b = (int)(gr / 9), n = (int)(gr - 9*(size_t)b);
            size_t base = (size_t)b*NSD + n*HID + aseg0*4;
            agp  = (sel ? g_ns1 : g_ns0) + base;
            agp2 = g_agg + base;
        }
    } else {
        if constexpr (MODE == 0) bgp = g_wt + (size_t)(col0 + brow)*FDIM;
        else                     bgp = g_wc + (size_t)brow*KB;
    }

    auto load_stage = [&](int s, int c){
        const uint32_t sb = sbase + (uint32_t)s*STAGE_BYTES;
        if (isA){
            const float* ap;
            if constexpr (MODE == 0) ap = agp + c*32;
            else                     ap = ((c < 8) ? agp : agp2) + (c & 7)*32;
            #pragma unroll
            for (int j = 0; j < 4; j++) CP16(sb + adst0 + j*16, ap + 4*j);
        } else {
            const float* bp = bgp + c*32;
            #pragma unroll
            for (int j = 0; j < 8; j++) CP16(sb + bdst0 + j*16, bp + 4*j);
        }
        CP_COMMIT();
    };

    // ---- fragment (ldmatrix) address setup: 16 warps = 2(M) x 8(N) ----
    const int mb = (wid & 1) * 64, nb = (wid >> 1) * 32;
    const int sub = lane >> 3;
    const int lrf = (sub & 1)*8 + (lane & 7);
    const int lca = (sub >> 1) * 16;
    uint32_t aoff[4];
    #pragma unroll
    for (int fm = 0; fm < 4; fm++)
        aoff[fm] = (uint32_t)(mb + fm*16 + lrf)*PADROW + lca;
    const int brf = (sub >> 1)*8 + (lane & 7);
    const int lcb = (sub & 1) * 16;
    uint32_t boff[2];
    #pragma unroll
    for (int p = 0; p < 2; p++)
        boff[p] = A_BYTES + (uint32_t)(nb + p*16 + brf)*PADROW + lcb;

    float acc[4][4][4];
    #pragma unroll
    for (int i=0;i<4;i++)
        #pragma unroll
        for (int j=0;j<4;j++)
            #pragma unroll
            for (int e=0;e<4;e++) acc[i][j][e] = 0.f;

    // ---- prologue: 3 of 4 stages in flight ----
    load_stage(0, 0); load_stage(1, 1); load_stage(2, 2);

    // ---- main loop ----
    for (int c = 0; c < NC; c++){
        CP_WAIT2();                 // all but 2 newest groups done -> chunk c landed
        __syncthreads();            // all warps past chunk c-1 -> stage (c+3)%4 free
        if (c + 3 < NC) load_stage((c + 3) % 4, c + 3);
        else            CP_COMMIT();   // keep group accounting uniform in tail

        const uint32_t stg = sbase + (uint32_t)(c & 3)*STAGE_BYTES;
        #pragma unroll
        for (int ks = 0; ks < 4; ks++){
            uint32_t a[4][4], b[4][2];
            #pragma unroll
            for (int fm = 0; fm < 4; fm++)
                LDSM4(a[fm][0], a[fm][1], a[fm][2], a[fm][3], stg + aoff[fm] + ks*32);
            #pragma unroll
            for (int p = 0; p < 2; p++)
                LDSM4(b[2*p][0], b[2*p][1], b[2*p+1][0], b[2*p+1][1], stg + boff[p] + ks*32);
            #pragma unroll
            for (int fm = 0; fm < 4; fm++)
                #pragma unroll
                for (int fn = 0; fn < 4; fn++)
                    mma8(acc[fm][fn], a[fm], b[fn][0], b[fn][1]);
        }
    }
    __syncthreads();   // everyone done with smem stages before epilogue reuse

    const int g = lane >> 2, tg = lane & 3;

    if constexpr (MODE == 0){
        // ---- init epilogue: + f2n_b + enc_b + logit*enc_w, straight to g_ns0 ----
        const int node = blockIdx.x;     // 256-col tile == one node
        #pragma unroll
        for (int fm = 0; fm < 4; fm++){
            const int gm = row0 + mb + fm*16 + g;
            const float lg0 = logits[gm*9 + node];
            const float lg1 = logits[(gm+8)*9 + node];
            float* dst0 = g_ns0 + (size_t)gm * NSD;
            float* dst1 = g_ns0 + (size_t)(gm + 8) * NSD;
            #pragma unroll
            for (int fn = 0; fn < 4; fn++){
                const int gn = col0 + nb + fn*8 + 2*tg;
                const int h = gn & 255;
                const float a0 = f2nb[gn]   + encb[h];
                const float a1 = f2nb[gn+1] + encb[h+1];
                const float e0 = encw[h], e1 = encw[h+1];
                float2 v0, v1;
                v0.x = f2t(acc[fm][fn][0] + a0 + lg0*e0);
                v0.y = f2t(acc[fm][fn][1] + a1 + lg0*e1);
                v1.x = f2t(acc[fm][fn][2] + a0 + lg1*e0);
                v1.y = f2t(acc[fm][fn][3] + a1 + lg1*e1);
                *(float2*)(dst0 + gn) = v0;
                *(float2*)(dst1 + gn) = v1;
            }
        }
    } else {
        // ---- step epilogue: tanh -> smem stage, then fused agg + stores ----
        float* sy = (float*)smem_raw;   // Y tile: 128 rows x SROW floats (133KB)
        #pragma unroll
        for (int fm = 0; fm < 4; fm++){
            const int r0l = mb + fm*16 + g;
            #pragma unroll
            for (int fn = 0; fn < 4; fn++){
                const int gn = nb + fn*8 + 2*tg;
                const float b0 = g_bc[gn], b1 = g_bc[gn+1];
                float2 v0, v1;
                v0.x = f2t(tanhf(acc[fm][fn][0] + b0));
                v0.y = f2t(tanhf(acc[fm][fn][1] + b1));
                v1.x = f2t(tanhf(acc[fm][fn][2] + b0));
                v1.y = f2t(tanhf(acc[fm][fn][3] + b1));
                *(float2*)(sy + (size_t)r0l*SROW + gn)     = v0;
                *(float2*)(sy + (size_t)(r0l+8)*SROW + gn) = v1;
            }
        }
        __syncthreads();

        float* dst = sel ? g_ns0 : g_ns1;
        const int nbat = (blockIdx.y*14 + 14 <= NB) ? 14 : (NB - blockIdx.y*14);
        // 14 batches x 64 col-quads = 896 items over 512 threads
        for (int idx = tid; idx < 14*64; idx += 512){
            const int lb = idx >> 6, c4 = (idx & 63) << 2;
            if (lb >= nbat) break;
            const size_t bglob = (size_t)(blockIdx.y*14 + lb);
            float4 v[9];
            #pragma unroll
            for (int j = 0; j < 9; j++)
                v[j] = *(float4*)(sy + (size_t)(lb*9 + j)*SROW + c4);
            float* nsb = dst + bglob*NSD + c4;
            #pragma unroll
            for (int j = 0; j < 9; j++)
                *(float4*)(nsb + j*HID) = v[j];
            if (write_agg){
                float4 sall = v[0];
                #pragma unroll
                for (int j = 1; j < 9; j++) sall = f4add(sall, v[j]);
                float* ab = g_agg + bglob*NSD + c4;
                *(float4*)(ab + 0*HID) = f2t4(f4scale(sall, 1.f/9.f));
                *(float4*)(ab + 1*HID) = f2t4(f4scale(f4add(v[0], v[1]), 0.5f));
                float4 b06 = f4add(v[0], f4add(v[7], v[8]));
                #pragma unroll
                for (int i = 2; i <= 6; i++)
                    *(float4*)(ab + i*HID) = f2t4(f4scale(f4add(b06, v[i]), 0.25f));
                float4 r78 = f2t4(f4scale(f4sub(sall, v[1]), 0.125f));
                *(float4*)(ab + 7*HID) = r78;
                *(float4*)(ab + 8*HID) = r78;
            }
        }
    }
}

// ---------------- output heads ----------------
__global__ void __launch_bounds__(256) out_k(const float* __restrict__ outw,
                                             const float* __restrict__ outb,
                                             float* __restrict__ out){
    int wid = threadIdx.x >> 5, lane = threadIdx.x & 31;
    int b = blockIdx.x * 8 + wid;
    const float* r7 = g_ns0 + (size_t)b*NSD + 7*HID;
    float s7 = 0.f, s8 = 0.f;
    #pragma unroll
    for (int i = lane; i < HID; i += 32){
        float w = outw[i];
        s7 += r7[i] * w;
        s8 += r7[i + HID] * w;
    }
    #pragma unroll
    for (int o = 16; o > 0; o >>= 1){
        s7 += __shfl_xor_sync(0xffffffffu, s7, o);
        s8 += __shfl_xor_sync(0xffffffffu, s8, o);
    }
    if (lane == 0){
        out[b]      = s7 + outb[0];
        out[NB + b] = s8 + outb[0];
    }
}

// ---------------- launch ----------------
extern "C" void kernel_launch(void* const* d_in, const int* in_sizes, int n_in,
                              void* d_out, int out_size){
    const float* conc   = (const float*)d_in[0];
    const float* logits = (const float*)d_in[1];
    const float* encw   = (const float*)d_in[2];
    const float* encb   = (const float*)d_in[3];
    const float* f2nw   = (const float*)d_in[4];
    const float* f2nb   = (const float*)d_in[5];
    const float* msgw   = (const float*)d_in[6];
    const float* msgb   = (const float*)d_in[7];
    const float* updw   = (const float*)d_in[8];
    const float* updb   = (const float*)d_in[9];
    const float* outw   = (const float*)d_in[10];
    const float* outb   = (const float*)d_in[11];
    float* out = (float*)d_out;

    cudaFuncSetAttribute(gemm_k<0>, cudaFuncAttributeMaxDynamicSharedMemorySize, SMEM_TOTAL);
    cudaFuncSetAttribute(gemm_k<1>, cudaFuncAttributeMaxDynamicSharedMemorySize, SMEM_TOTAL);

    prep_k<<<256, 256>>>(msgw, msgb, updw, updb);
    round_conc_k<<<(NB*(FDIM/4))/256, 256>>>(conc);
    round_w_k<<<(NSD*(FDIM/4))/256, 256>>>(f2nw);

    // init: node_states -> g_ns0  (grid: 9 N-blocks x 128 M-blocks)
    gemm_k<0><<<dim3(NSD/256, NB/128), 512, SMEM_TOTAL>>>(f2nb, logits, encw, encb, 0, 0);

    // first aggregate (from initial states)
    agg_k<<<(NB*64)/256, 256>>>(0);

    // 4 steps; ping-pong ns0/ns1; steps 0..2 also emit next step's agg in-epilogue
    const int MB1 = (NB + 13) / 14;   // 1171 batch-aligned M-blocks
    for (int s = 0; s < 4; s++){
        gemm_k<1><<<dim3(1, MB1), 512, SMEM_TOTAL>>>(nullptr, nullptr, nullptr, nullptr,
                                                     s & 1, (s < 3) ? 1 : 0);
    }

    out_k<<<NB/8, 256>>>(outw, outb, out);
}